// round 7
// baseline (speedup 1.0000x reference)
#include <cuda_runtime.h>
#include <cuda_bf16.h>
#include <cstdint>

// Problem constants
#define NTOK   8192
#define DMODEL 4096
#define DSAE   16384
#define KSP    64

#define BAND_EPS 2e-4f   // boundary-ambiguity band on pre_act value scale

// d_out layout: [recon (NTOK*DMODEL) | sparse (NTOK*DSAE) | pre (NTOK*DSAE)]

// ---------------- scratch (__device__ globals — sanctioned scratch) ----------------
__device__ float g_WdecT[(size_t)DSAE * DMODEL];   // 256 MB transposed decoder weights
__device__ int   g_topidx[(size_t)NTOK * KSP];
__device__ float g_topval[(size_t)NTOK * KSP];
__device__ float g_vT[NTOK];      // per-token rank-64 threshold value
__device__ int   g_flag[NTOK];    // per-token "needs exact refinement"

// ---------------- f32x2 packed-FMA helpers ----------------
__device__ __forceinline__ unsigned long long pack2(float x, float y) {
    unsigned long long r;
    asm("mov.b64 %0, {%1, %2};" : "=l"(r) : "f"(x), "f"(y));
    return r;
}
__device__ __forceinline__ void unpack2(float& x, float& y, unsigned long long v) {
    asm("mov.b64 {%0, %1}, %2;" : "=f"(x), "=f"(y) : "l"(v));
}
#define FMA2(d, a, b, c) \
    asm("fma.rn.f32x2 %0, %1, %2, %3;" : "=l"(d) : "l"(a), "l"(b), "l"(c))

// =====================================================================
// Kernel 1: encoder GEMM  pre[m,f] = sum_k x[m,k]*W_enc[f,k] + b_enc[f]
// Serial ascending-k fp32 FMA per output. BM=BN=128, BK=16, 256 thr.
// =====================================================================
#define BM 128
#define BN 128
#define BK 16

__global__ __launch_bounds__(256, 2)
void enc_gemm(const float* __restrict__ A,     // x: NTOK x DMODEL
              const float* __restrict__ B,     // W_enc: DSAE x DMODEL
              const float* __restrict__ bias,  // DSAE
              float* __restrict__ C)           // pre: NTOK x DSAE
{
    __shared__ float As[BK][BM + 4];
    __shared__ float Bs[BK][BN + 4];

    const int tid = threadIdx.x;
    const int bx = blockIdx.x;   // feature tile
    const int by = blockIdx.y;   // token tile
    const int tx = tid & 15;
    const int ty = tid >> 4;

    const float* Ag = A + (size_t)(by * BM) * DMODEL;
    const float* Bg = B + (size_t)(bx * BN) * DMODEL;

    unsigned long long acc[8][4];
#pragma unroll
    for (int i = 0; i < 8; i++)
#pragma unroll
        for (int j = 0; j < 4; j++) acc[i][j] = 0ULL;

    for (int k0 = 0; k0 < DMODEL; k0 += BK) {
#pragma unroll
        for (int h = 0; h < 2; h++) {
            int id  = tid + h * 256;
            int row = id >> 2;
            int c4  = id & 3;
            float4 va = *(const float4*)(Ag + (size_t)row * DMODEL + k0 + c4 * 4);
            As[c4 * 4 + 0][row] = va.x;
            As[c4 * 4 + 1][row] = va.y;
            As[c4 * 4 + 2][row] = va.z;
            As[c4 * 4 + 3][row] = va.w;
            float4 vb = *(const float4*)(Bg + (size_t)row * DMODEL + k0 + c4 * 4);
            Bs[c4 * 4 + 0][row] = vb.x;
            Bs[c4 * 4 + 1][row] = vb.y;
            Bs[c4 * 4 + 2][row] = vb.z;
            Bs[c4 * 4 + 3][row] = vb.w;
        }
        __syncthreads();

#pragma unroll
        for (int kk = 0; kk < BK; kk++) {
            float4 a0 = *(const float4*)&As[kk][ty * 8];
            float4 a1 = *(const float4*)&As[kk][ty * 8 + 4];
            float4 b0 = *(const float4*)&Bs[kk][tx * 8];
            float4 b1 = *(const float4*)&Bs[kk][tx * 8 + 4];
            unsigned long long bp[4];
            bp[0] = pack2(b0.x, b0.y);
            bp[1] = pack2(b0.z, b0.w);
            bp[2] = pack2(b1.x, b1.y);
            bp[3] = pack2(b1.z, b1.w);
            float av[8] = {a0.x, a0.y, a0.z, a0.w, a1.x, a1.y, a1.z, a1.w};
#pragma unroll
            for (int i = 0; i < 8; i++) {
                unsigned long long as = pack2(av[i], av[i]);
#pragma unroll
                for (int j = 0; j < 4; j++) FMA2(acc[i][j], as, bp[j], acc[i][j]);
            }
        }
        __syncthreads();
    }

    const int crow = by * BM + ty * 8;
    const int ccol = bx * BN + tx * 8;
    float bb[8];
    {
        float4 v0 = *(const float4*)&bias[ccol];
        float4 v1 = *(const float4*)&bias[ccol + 4];
        bb[0] = v0.x; bb[1] = v0.y; bb[2] = v0.z; bb[3] = v0.w;
        bb[4] = v1.x; bb[5] = v1.y; bb[6] = v1.z; bb[7] = v1.w;
    }
#pragma unroll
    for (int i = 0; i < 8; i++) {
        float o[8];
#pragma unroll
        for (int j = 0; j < 4; j++) unpack2(o[2 * j], o[2 * j + 1], acc[i][j]);
#pragma unroll
        for (int q = 0; q < 8; q++) o[q] += bb[q];
        float* cp = C + (size_t)(crow + i) * DSAE + ccol;
        *(float4*)cp       = make_float4(o[0], o[1], o[2], o[3]);
        *(float4*)(cp + 4) = make_float4(o[4], o[5], o[6], o[7]);
    }
}

// =====================================================================
// Kernel 2: transpose W_dec (DMODEL x DSAE) -> g_WdecT (DSAE x DMODEL)
// =====================================================================
__global__ __launch_bounds__(256)
void wdec_transpose(const float* __restrict__ W)   // W[d*DSAE + f]
{
    __shared__ float s[32][33];
    const int f0 = blockIdx.x * 32;
    const int d0 = blockIdx.y * 32;
    const int tx = threadIdx.x;     // 0..31
    const int ty = threadIdx.y;     // 0..7
#pragma unroll
    for (int j = 0; j < 32; j += 8)
        s[ty + j][tx] = W[(size_t)(d0 + ty + j) * DSAE + f0 + tx];
    __syncthreads();
#pragma unroll
    for (int j = 0; j < 32; j += 8)
        g_WdecT[(size_t)(f0 + ty + j) * DMODEL + d0 + tx] = s[tx][ty + j];
}

// =====================================================================
// Kernel 3: per-token top-64 radix select (exact on our fp32 values,
// lowest-index tie-break), writes sparse row + compacted lists,
// plus per-token threshold value and refinement flag.
// =====================================================================
__device__ __forceinline__ unsigned int fkey(float x) {
    unsigned int u = __float_as_uint(x);
    unsigned int m = ((unsigned int)((int)u >> 31)) | 0x80000000u;
    return u ^ m;   // monotone float -> uint
}
__device__ __forceinline__ float keyval(unsigned int k) {
    unsigned int u = (k & 0x80000000u) ? (k ^ 0x80000000u) : ~k;
    return __uint_as_float(u);
}

__global__ __launch_bounds__(256)
void topk_select(const float* __restrict__ pre,   // NTOK x DSAE
                 float* __restrict__ sparse)      // NTOK x DSAE
{
    extern __shared__ float srow[];               // DSAE floats = 64KB
    __shared__ unsigned int hist[8][256];         // 8KB
    __shared__ unsigned int bitmap[DSAE / 32];    // 2KB
    __shared__ int s_gt[256], s_eq[256], s_base[256], s_ebase[256];
    __shared__ unsigned int sh_pfx;
    __shared__ int sh_need;
    __shared__ int s_flag;

    const int token = blockIdx.x;
    const int tid = threadIdx.x;
    const int wid = tid >> 5;
    const float* prow = pre + (size_t)token * DSAE;

    // stage row
    for (int i = tid; i < DSAE; i += 256) srow[i] = prow[i];
    __syncthreads();

    // 4-round radix select (byte-wise, high->low) for the 64th-largest key
    unsigned int pfx = 0;
    int need = KSP;
    for (int b = 3; b >= 0; --b) {
        for (int i = tid; i < 8 * 256; i += 256) ((unsigned int*)hist)[i] = 0;
        __syncthreads();
        const int sh = b * 8;
        for (int i = tid; i < DSAE; i += 256) {
            unsigned int k = fkey(srow[i]);
            bool m = (b == 3) || ((k >> (sh + 8)) == pfx);
            if (m) atomicAdd(&hist[wid][(k >> sh) & 255], 1u);
        }
        __syncthreads();
        if (tid < 256) {
            unsigned int s = 0;
#pragma unroll
            for (int w = 0; w < 8; w++) s += hist[w][tid];
            hist[0][tid] = s;
        }
        __syncthreads();
        if (tid == 0) {
            int cum = 0, v = 255;
            for (; v > 0; --v) {
                int c = (int)hist[0][v];
                if (cum + c >= need) break;
                cum += c;
            }
            sh_pfx = (pfx << 8) | (unsigned int)v;
            sh_need = need - cum;
        }
        __syncthreads();
        pfx = sh_pfx;
        need = sh_need;
        __syncthreads();
    }
    const unsigned int T = pfx;   // threshold key (64th largest)
    const int r = need;           // # of keys == T to take (lowest indices)
    const float vT = keyval(T);   // threshold value

    // pass 1: per-segment counts (each thread owns 64 contiguous elems)
    const int seg = tid * 64;
    {
        int ngt = 0, neq = 0;
#pragma unroll 4
        for (int ii = 0; ii < 64; ii++) {
            unsigned int k = fkey(srow[seg + ii]);
            ngt += (k > T);
            neq += (k == T);
        }
        s_gt[tid] = ngt;
        s_eq[tid] = neq;
    }
    if (tid == 0) s_flag = 0;
    __syncthreads();
    if (tid == 0) {
        int eacc = 0, sacc = 0;
        for (int q = 0; q < 256; q++) {
            s_ebase[q] = eacc;
            int etake = r - eacc;
            if (etake < 0) etake = 0;
            if (etake > s_eq[q]) etake = s_eq[q];
            s_base[q] = sacc;
            sacc += s_gt[q] + etake;
            eacc += s_eq[q];
        }
    }
    __syncthreads();

    // pass 2: deterministic compaction (index-ascending) + bitmap
    {
        unsigned int bits0 = 0, bits1 = 0;
        int p = s_base[tid];
        int e = s_ebase[tid];
        int*   oidx = g_topidx + (size_t)token * KSP;
        float* oval = g_topval + (size_t)token * KSP;
        for (int ii = 0; ii < 64; ii++) {
            int i = seg + ii;
            float x = srow[i];
            unsigned int k = fkey(x);
            bool gt = (k > T);
            bool eq = (k == T);
            bool take = gt || (eq && e < r);
            if (eq) e++;
            if (take) {
                oidx[p] = i;
                oval[p] = x;
                if (ii < 32) bits0 |= (1u << ii);
                else         bits1 |= (1u << (ii - 32));
                p++;
            }
        }
        bitmap[tid * 2]     = bits0;
        bitmap[tid * 2 + 1] = bits1;
    }
    __syncthreads();

    // pass 3: coalesced sparse row write + ambiguity detection
    float* srow_out = sparse + (size_t)token * DSAE;
    for (int i = tid; i < DSAE; i += 256) {
        bool sel = (bitmap[i >> 5] >> (i & 31)) & 1u;
        float v = srow[i];
        srow_out[i] = sel ? v : 0.0f;
        // an unselected element inside the band => the boundary choice is
        // within fp32 accumulation-noise of the reference => refine exactly
        if (!sel && fabsf(v - vT) <= BAND_EPS) s_flag = 1;
    }
    __syncthreads();
    if (tid == 0) {
        g_vT[token] = vT;
        g_flag[token] = s_flag;
    }
}

// =====================================================================
// Kernel 3b: exact boundary refinement. For flagged tokens (~500 of
// 8192), recompute the ambiguous candidates' dot products in fp64,
// round to fp32 (mimics an accurate fp32 reference incl. tie-stability),
// and rebuild the top-64 set + outputs.
// =====================================================================
__global__ __launch_bounds__(256)
void refine(const float* __restrict__ pre,
            const float* __restrict__ x,
            const float* __restrict__ Wenc,
            float* __restrict__ sparse)
{
    extern __shared__ float srow[];               // DSAE floats = 64KB
    __shared__ int    s_band[64];
    __shared__ float  s_ef[64];
    __shared__ double s_red[256];
    __shared__ unsigned int bm[DSAE / 32];
    __shared__ int s_cnt[256], s_base[256];
    __shared__ int s_chosen[64];
    __shared__ int s_nin, s_c, s_nch;

    const int token = blockIdx.x;
    if (!g_flag[token]) return;                   // uniform across block

    const int tid = threadIdx.x;
    const float vT = g_vT[token];
    const float* prow = pre + (size_t)token * DSAE;

    for (int i = tid; i < DSAE; i += 256) srow[i] = prow[i];
    if (tid == 0) { s_nin = 0; s_c = 0; }
    __syncthreads();

    // classify: certain-in (> vT+EPS) vs band (|v - vT| <= EPS)
    int nin_local = 0;
    for (int i = tid; i < DSAE; i += 256) {
        float v = srow[i];
        if (v > vT + BAND_EPS) {
            nin_local++;
        } else if (fabsf(v - vT) <= BAND_EPS) {
            int p = atomicAdd(&s_c, 1);
            if (p < 64) s_band[p] = i;
        }
    }
    atomicAdd(&s_nin, nin_local);
    __syncthreads();

    const int c = min(s_c, 64);
    const int need = KSP - s_nin;                 // band slots in the top-64 (>=1)

    // sort band by index ascending (stable tie-break later)
    if (tid == 0) {
        for (int a = 1; a < c; a++) {
            int key = s_band[a], b = a - 1;
            for (; b >= 0 && s_band[b] > key; b--) s_band[b + 1] = s_band[b];
            s_band[b + 1] = key;
        }
    }
    __syncthreads();

    // exact fp64 dot per candidate, rounded to fp32
    const float* xr = x + (size_t)token * DMODEL;
    for (int j = 0; j < c; j++) {
        const float* wr = Wenc + (size_t)s_band[j] * DMODEL;
        double p = 0.0;
        for (int d = tid; d < DMODEL; d += 256)
            p += (double)xr[d] * (double)wr[d];
        s_red[tid] = p;
        __syncthreads();
        for (int off = 128; off > 0; off >>= 1) {
            if (tid < off) s_red[tid] += s_red[tid + off];
            __syncthreads();
        }
        if (tid == 0) s_ef[j] = (float)s_red[0];
        __syncthreads();
    }

    // choose top-'need' among band by (value desc, index asc)
    if (tid == 0) {
        bool used[64];
        for (int j = 0; j < c; j++) used[j] = false;
        int nc = 0;
        for (int t = 0; t < need && t < c; t++) {
            int best = -1;
            for (int j = 0; j < c; j++)
                if (!used[j] && (best < 0 || s_ef[j] > s_ef[best])) best = j;
            used[best] = true;
            s_chosen[nc++] = s_band[best];
        }
        s_nch = nc;
    }
    __syncthreads();

    // rebuild bitmap: certain-in bits per thread segment, then chosen band bits
    {
        int seg = tid * 64;
        unsigned int b0 = 0, b1 = 0;
        for (int ii = 0; ii < 64; ii++) {
            float v = srow[seg + ii];
            if (v > vT + BAND_EPS) {
                if (ii < 32) b0 |= (1u << ii);
                else         b1 |= (1u << (ii - 32));
            }
        }
        bm[tid * 2]     = b0;
        bm[tid * 2 + 1] = b1;
    }
    __syncthreads();
    if (tid == 0)
        for (int t = 0; t < s_nch; t++) {
            int i = s_chosen[t];
            bm[i >> 5] |= (1u << (i & 31));
        }
    __syncthreads();

    // prefix for index-ascending compaction
    s_cnt[tid] = __popc(bm[tid * 2]) + __popc(bm[tid * 2 + 1]);
    __syncthreads();
    if (tid == 0) {
        int acc = 0;
        for (int q = 0; q < 256; q++) { s_base[q] = acc; acc += s_cnt[q]; }
    }
    __syncthreads();

    // emit corrected sparse row + compacted lists
    float* srow_out = sparse + (size_t)token * DSAE;
    int*   oidx = g_topidx + (size_t)token * KSP;
    float* oval = g_topval + (size_t)token * KSP;
    {
        int seg = tid * 64;
        int p = s_base[tid];
        for (int ii = 0; ii < 64; ii++) {
            int i = seg + ii;
            bool sel = (bm[i >> 5] >> (i & 31)) & 1u;
            srow_out[i] = sel ? srow[i] : 0.0f;
            if (sel) { oidx[p] = i; oval[p] = srow[i]; p++; }
        }
    }
}

// =====================================================================
// Kernel 4: sparse decoder. One block per (token, 1024-col chunk).
// grid.y slow => all tokens for one chunk together => W_decT chunk
// (64MB) stays L2-resident.
// =====================================================================
__global__ __launch_bounds__(256)
void sparse_decode(const float* __restrict__ bdec,
                   float* __restrict__ recon)     // NTOK x DMODEL
{
    const int token = blockIdx.x;
    const int chunk = blockIdx.y * 1024;
    const int t = threadIdx.x;

    __shared__ int   fi[KSP];
    __shared__ float fv[KSP];
    if (t < KSP) {
        fi[t] = g_topidx[(size_t)token * KSP + t];
        fv[t] = g_topval[(size_t)token * KSP + t];
    }
    __syncthreads();

    float a0 = bdec[chunk + t];
    float a1 = bdec[chunk + 256 + t];
    float a2 = bdec[chunk + 512 + t];
    float a3 = bdec[chunk + 768 + t];

#pragma unroll 4
    for (int j = 0; j < KSP; j++) {
        const float* w = g_WdecT + (size_t)fi[j] * DMODEL + chunk;
        float v = fv[j];
        a0 = fmaf(v, w[t], a0);
        a1 = fmaf(v, w[256 + t], a1);
        a2 = fmaf(v, w[512 + t], a2);
        a3 = fmaf(v, w[768 + t], a3);
    }

    float* o = recon + (size_t)token * DMODEL + chunk;
    o[t]       = a0;
    o[256 + t] = a1;
    o[512 + t] = a2;
    o[768 + t] = a3;
}

// =====================================================================
// launch
// =====================================================================
extern "C" void kernel_launch(void* const* d_in, const int* in_sizes, int n_in,
                              void* d_out, int out_size)
{
    const float* x     = (const float*)d_in[0];
    const float* W_enc = (const float*)d_in[1];
    const float* b_enc = (const float*)d_in[2];
    const float* W_dec = (const float*)d_in[3];
    const float* b_dec = (const float*)d_in[4];

    float* out    = (float*)d_out;
    float* recon  = out;
    float* sparse = out + (size_t)NTOK * DMODEL;
    float* pre    = sparse + (size_t)NTOK * DSAE;

    cudaFuncSetAttribute(topk_select, cudaFuncAttributeMaxDynamicSharedMemorySize,
                         DSAE * (int)sizeof(float));
    cudaFuncSetAttribute(refine, cudaFuncAttributeMaxDynamicSharedMemorySize,
                         DSAE * (int)sizeof(float));

    // encoder GEMM -> pre_acts (serial ascending-k fp32 FMA)
    enc_gemm<<<dim3(DSAE / BN, NTOK / BM), 256>>>(x, W_enc, b_enc, pre);

    // transpose decoder weights (independent of encoder result)
    wdec_transpose<<<dim3(DSAE / 32, DMODEL / 32), dim3(32, 8)>>>(W_dec);

    // per-token top-64 -> sparse_acts + compacted lists + ambiguity flags
    topk_select<<<NTOK, 256, DSAE * sizeof(float)>>>(pre, sparse);

    // exact fp64 boundary refinement for ambiguous tokens (~500 blocks do work)
    refine<<<NTOK, 256, DSAE * sizeof(float)>>>(pre, x, W_enc, sparse);

    // sparse decode -> reconstruction
    sparse_decode<<<dim3(NTOK, DMODEL / 1024), 256>>>(b_dec, recon);
}

// round 9
// speedup vs baseline: 1.4695x; 1.4695x over previous
#include <cuda_runtime.h>
#include <cuda_bf16.h>
#include <cstdint>

// Problem constants
#define NTOK   8192
#define DMODEL 4096
#define DSAE   16384
#define KSP    64

#define BAND_EPS 2e-4f   // boundary-ambiguity band on pre_act value scale

// d_out layout: [recon (NTOK*DMODEL) | sparse (NTOK*DSAE) | pre (NTOK*DSAE)]

// ---------------- scratch (__device__ globals) ----------------
__device__ float g_WdecT[(size_t)DSAE * DMODEL];   // 256 MB transposed decoder weights
__device__ int   g_topidx[(size_t)NTOK * KSP];
__device__ float g_topval[(size_t)NTOK * KSP];
__device__ float g_vT[NTOK];
__device__ int   g_flag[NTOK];
// bf16 split operands for tensor-core encoder
__device__ __nv_bfloat16 g_Ahi[(size_t)NTOK * DMODEL];   // 64 MB
__device__ __nv_bfloat16 g_Amid[(size_t)NTOK * DMODEL];  // 64 MB
__device__ __nv_bfloat16 g_Bhi[(size_t)DSAE * DMODEL];   // 128 MB
__device__ __nv_bfloat16 g_Bmid[(size_t)DSAE * DMODEL];  // 128 MB

// ---------------- baseline-PTX helpers (sm_80-level only; NO _a features) -----
__device__ __forceinline__ uint32_t smem_to_u32(const void* p) {
    uint32_t a;
    asm("{ .reg .u64 t; cvta.to.shared.u64 t, %1; cvt.u32.u64 %0, t; }"
        : "=r"(a) : "l"(p));
    return a;
}
__device__ __forceinline__ void cp_async16(uint32_t saddr, const void* gaddr) {
    asm volatile("cp.async.cg.shared.global [%0], [%1], 16;" :: "r"(saddr), "l"(gaddr));
}
#define CP_COMMIT() asm volatile("cp.async.commit_group;" ::: "memory")
template <int N>
__device__ __forceinline__ void cp_wait_group() {
    asm volatile("cp.async.wait_group %0;" :: "n"(N) : "memory");
}

// mma.sync m16n8k16 row.col bf16 -> f32 (PTX ISA 7.0, baseline sm_80)
__device__ __forceinline__ void mma16816(float* d, const uint32_t* a, const uint32_t* b) {
    asm volatile(
        "mma.sync.aligned.m16n8k16.row.col.f32.bf16.bf16.f32 "
        "{%0,%1,%2,%3}, {%4,%5,%6,%7}, {%8,%9}, {%0,%1,%2,%3};"
        : "+f"(d[0]), "+f"(d[1]), "+f"(d[2]), "+f"(d[3])
        : "r"(a[0]), "r"(a[1]), "r"(a[2]), "r"(a[3]), "r"(b[0]), "r"(b[1]));
}

// =====================================================================
// Kernel 0: bf16 two-way split (hi = rn(v), mid = rn(v - hi))
// =====================================================================
__global__ __launch_bounds__(256)
void split_pair(const float* __restrict__ src, __nv_bfloat16* __restrict__ hi,
                __nv_bfloat16* __restrict__ mid, size_t n)
{
    size_t i = (size_t)blockIdx.x * 256 + threadIdx.x;
    size_t stride = (size_t)gridDim.x * 256;
    for (; i < n; i += stride) {
        float v = src[i];
        __nv_bfloat16 h = __float2bfloat16(v);
        float hf = __bfloat162float(h);
        hi[i] = h;
        mid[i] = __float2bfloat16(v - hf);
    }
}

// =====================================================================
// Kernel 1: HMMA encoder GEMM (bf16x3 split):
//   pre = Ahi·Bhi^T + Ahi·Bmid^T + Amid·Bhi^T + bias  (fp32 accum)
// BM=128, BN=128, BK=64, 2-stage cp.async double buffer, 256 threads.
// Each of 8 warps computes a 64x32 sub-tile via m16n8k16.
// Smem rows padded to 144B so frag LDS (banks = 4g+tg+c) is conflict-free.
// =====================================================================
#define HB_BM 128
#define HB_BN 128
#define HB_BK 64
#define HB_RSB 144                      // row stride bytes (64*2 data + 16 pad)
#define HB_MAT (128 * HB_RSB)           // 18432 B per matrix tile
#define HB_STAGE (4 * HB_MAT)           // Ahi/Amid/Bhi/Bmid = 73728 B
#define HB_SMEM (2 * HB_STAGE)          // 147456 B
#define OFF_AHI  0
#define OFF_AMID HB_MAT
#define OFF_BHI  (2 * HB_MAT)
#define OFF_BMID (3 * HB_MAT)

__global__ __launch_bounds__(256, 1)
void enc_hmma(const float* __restrict__ bias, float* __restrict__ C)
{
    extern __shared__ char smem[];
    const int tid  = threadIdx.x;
    const int wid  = tid >> 5;
    const int lane = tid & 31;

    // rasterize: groups of 8 M-tiles x all 128 N-tiles (A slice L2-resident)
    const int t  = blockIdx.x;
    const int g  = t >> 10;             // /(8*128)
    const int r  = t & 1023;
    const int mt = (g << 3) + (r & 7);
    const int nt = r >> 3;
    const int m0 = mt * HB_BM;
    const int n0 = nt * HB_BN;

    const int warp_m = (wid >> 2) * 64;   // 0 / 64
    const int warp_n = (wid & 3) * 32;    // 0..96

    float acc[4][4][4];
#pragma unroll
    for (int i = 0; i < 4; i++)
#pragma unroll
        for (int j = 0; j < 4; j++)
#pragma unroll
            for (int q = 0; q < 4; q++) acc[i][j][q] = 0.0f;

    const char* gbase[4] = {
        (const char*)g_Ahi  + (size_t)m0 * DMODEL * 2,
        (const char*)g_Amid + (size_t)m0 * DMODEL * 2,
        (const char*)g_Bhi  + (size_t)n0 * DMODEL * 2,
        (const char*)g_Bmid + (size_t)n0 * DMODEL * 2
    };
    const uint32_t sb = smem_to_u32(smem);

    const int NCH = DMODEL / HB_BK;     // 64

    // ---- stage loader: 4096 16B chunks, 16 per thread ----
    auto load_stage = [&](int ch, int s) {
        const uint32_t stg = sb + s * HB_STAGE;
        const int k0 = ch * HB_BK;
#pragma unroll
        for (int i = 0; i < 16; i++) {
            int c     = tid + i * 256;
            int mat   = c >> 10;
            int rem   = c & 1023;
            int row   = rem >> 3;
            int col16 = rem & 7;
            cp_async16(stg + mat * HB_MAT + row * HB_RSB + col16 * 16,
                       gbase[mat] + (size_t)row * (DMODEL * 2) + k0 * 2 + col16 * 16);
        }
        CP_COMMIT();
    };

    load_stage(0, 0);

    const int gg = lane >> 2;           // fragment row/col group
    const int tg = lane & 3;

    for (int ch = 0; ch < NCH; ch++) {
        if (ch + 1 < NCH) {
            load_stage(ch + 1, (ch + 1) & 1);
            cp_wait_group<1>();
        } else {
            cp_wait_group<0>();
        }
        __syncthreads();

        const char* stg   = smem + (ch & 1) * HB_STAGE;
        const char* sAhi  = stg + OFF_AHI;
        const char* sAmid = stg + OFF_AMID;
        const char* sBhi  = stg + OFF_BHI;
        const char* sBmid = stg + OFF_BMID;

#pragma unroll
        for (int ks = 0; ks < 4; ks++) {
            const int kb = ks * 32;     // 16 bf16 = 32 bytes per k-step
            uint32_t a_hi[4][4], a_mid[4][4], b_hi[4][2], b_mid[4][2];
#pragma unroll
            for (int i = 0; i < 4; i++) {
                int base = (warp_m + i * 16 + gg) * HB_RSB + kb + tg * 4;
                a_hi[i][0]  = *(const uint32_t*)(sAhi  + base);
                a_hi[i][1]  = *(const uint32_t*)(sAhi  + base + 8 * HB_RSB);
                a_hi[i][2]  = *(const uint32_t*)(sAhi  + base + 16);
                a_hi[i][3]  = *(const uint32_t*)(sAhi  + base + 8 * HB_RSB + 16);
                a_mid[i][0] = *(const uint32_t*)(sAmid + base);
                a_mid[i][1] = *(const uint32_t*)(sAmid + base + 8 * HB_RSB);
                a_mid[i][2] = *(const uint32_t*)(sAmid + base + 16);
                a_mid[i][3] = *(const uint32_t*)(sAmid + base + 8 * HB_RSB + 16);
            }
#pragma unroll
            for (int j = 0; j < 4; j++) {
                int base = (warp_n + j * 8 + gg) * HB_RSB + kb + tg * 4;
                b_hi[j][0]  = *(const uint32_t*)(sBhi  + base);
                b_hi[j][1]  = *(const uint32_t*)(sBhi  + base + 16);
                b_mid[j][0] = *(const uint32_t*)(sBmid + base);
                b_mid[j][1] = *(const uint32_t*)(sBmid + base + 16);
            }
#pragma unroll
            for (int i = 0; i < 4; i++)
#pragma unroll
                for (int j = 0; j < 4; j++) {
                    mma16816(acc[i][j], a_hi[i],  b_hi[j]);
                    mma16816(acc[i][j], a_hi[i],  b_mid[j]);
                    mma16816(acc[i][j], a_mid[i], b_hi[j]);
                }
        }
        __syncthreads();
    }

    // ---- epilogue: bias add + store ----
#pragma unroll
    for (int i = 0; i < 4; i++) {
        const int row0 = m0 + warp_m + i * 16 + gg;
#pragma unroll
        for (int j = 0; j < 4; j++) {
            const int col = n0 + warp_n + j * 8 + tg * 2;
            const float b0 = bias[col];
            const float b1 = bias[col + 1];
            float* p0 = C + (size_t)row0 * DSAE + col;
            float* p1 = C + (size_t)(row0 + 8) * DSAE + col;
            *(float2*)p0 = make_float2(acc[i][j][0] + b0, acc[i][j][1] + b1);
            *(float2*)p1 = make_float2(acc[i][j][2] + b0, acc[i][j][3] + b1);
        }
    }
}

// =====================================================================
// Kernel 2: transpose W_dec (DMODEL x DSAE) -> g_WdecT (DSAE x DMODEL)
// =====================================================================
__global__ __launch_bounds__(256)
void wdec_transpose(const float* __restrict__ W)
{
    __shared__ float s[32][33];
    const int f0 = blockIdx.x * 32;
    const int d0 = blockIdx.y * 32;
    const int tx = threadIdx.x;
    const int ty = threadIdx.y;
#pragma unroll
    for (int j = 0; j < 32; j += 8)
        s[ty + j][tx] = W[(size_t)(d0 + ty + j) * DSAE + f0 + tx];
    __syncthreads();
#pragma unroll
    for (int j = 0; j < 32; j += 8)
        g_WdecT[(size_t)(f0 + ty + j) * DMODEL + d0 + tx] = s[tx][ty + j];
}

// =====================================================================
// Kernel 3: per-token top-64 radix select (exact on our fp32 values,
// lowest-index tie-break) + ambiguity flagging
// =====================================================================
__device__ __forceinline__ unsigned int fkey(float x) {
    unsigned int u = __float_as_uint(x);
    unsigned int m = ((unsigned int)((int)u >> 31)) | 0x80000000u;
    return u ^ m;
}
__device__ __forceinline__ float keyval(unsigned int k) {
    unsigned int u = (k & 0x80000000u) ? (k ^ 0x80000000u) : ~k;
    return __uint_as_float(u);
}

__global__ __launch_bounds__(256)
void topk_select(const float* __restrict__ pre, float* __restrict__ sparse)
{
    extern __shared__ float srow[];
    __shared__ unsigned int hist[8][256];
    __shared__ unsigned int bitmap[DSAE / 32];
    __shared__ int s_gt[256], s_eq[256], s_base[256], s_ebase[256];
    __shared__ unsigned int sh_pfx;
    __shared__ int sh_need;
    __shared__ int s_flag;

    const int token = blockIdx.x;
    const int tid = threadIdx.x;
    const int wid = tid >> 5;
    const float* prow = pre + (size_t)token * DSAE;

    for (int i = tid; i < DSAE; i += 256) srow[i] = prow[i];
    __syncthreads();

    unsigned int pfx = 0;
    int need = KSP;
    for (int b = 3; b >= 0; --b) {
        for (int i = tid; i < 8 * 256; i += 256) ((unsigned int*)hist)[i] = 0;
        __syncthreads();
        const int sh = b * 8;
        for (int i = tid; i < DSAE; i += 256) {
            unsigned int k = fkey(srow[i]);
            bool m = (b == 3) || ((k >> (sh + 8)) == pfx);
            if (m) atomicAdd(&hist[wid][(k >> sh) & 255], 1u);
        }
        __syncthreads();
        if (tid < 256) {
            unsigned int s = 0;
#pragma unroll
            for (int w = 0; w < 8; w++) s += hist[w][tid];
            hist[0][tid] = s;
        }
        __syncthreads();
        if (tid == 0) {
            int cum = 0, v = 255;
            for (; v > 0; --v) {
                int c = (int)hist[0][v];
                if (cum + c >= need) break;
                cum += c;
            }
            sh_pfx = (pfx << 8) | (unsigned int)v;
            sh_need = need - cum;
        }
        __syncthreads();
        pfx = sh_pfx;
        need = sh_need;
        __syncthreads();
    }
    const unsigned int T = pfx;
    const int r = need;
    const float vT = keyval(T);

    const int seg = tid * 64;
    {
        int ngt = 0, neq = 0;
#pragma unroll 4
        for (int ii = 0; ii < 64; ii++) {
            unsigned int k = fkey(srow[seg + ii]);
            ngt += (k > T);
            neq += (k == T);
        }
        s_gt[tid] = ngt;
        s_eq[tid] = neq;
    }
    if (tid == 0) s_flag = 0;
    __syncthreads();
    if (tid == 0) {
        int eacc = 0, sacc = 0;
        for (int q = 0; q < 256; q++) {
            s_ebase[q] = eacc;
            int etake = r - eacc;
            if (etake < 0) etake = 0;
            if (etake > s_eq[q]) etake = s_eq[q];
            s_base[q] = sacc;
            sacc += s_gt[q] + etake;
            eacc += s_eq[q];
        }
    }
    __syncthreads();

    {
        unsigned int bits0 = 0, bits1 = 0;
        int p = s_base[tid];
        int e = s_ebase[tid];
        int*   oidx = g_topidx + (size_t)token * KSP;
        float* oval = g_topval + (size_t)token * KSP;
        for (int ii = 0; ii < 64; ii++) {
            int i = seg + ii;
            float x = srow[i];
            unsigned int k = fkey(x);
            bool gt = (k > T);
            bool eq = (k == T);
            bool take = gt || (eq && e < r);
            if (eq) e++;
            if (take) {
                oidx[p] = i;
                oval[p] = x;
                if (ii < 32) bits0 |= (1u << ii);
                else         bits1 |= (1u << (ii - 32));
                p++;
            }
        }
        bitmap[tid * 2]     = bits0;
        bitmap[tid * 2 + 1] = bits1;
    }
    __syncthreads();

    float* srow_out = sparse + (size_t)token * DSAE;
    for (int i = tid; i < DSAE; i += 256) {
        bool sel = (bitmap[i >> 5] >> (i & 31)) & 1u;
        float v = srow[i];
        srow_out[i] = sel ? v : 0.0f;
        if (!sel && fabsf(v - vT) <= BAND_EPS) s_flag = 1;
    }
    __syncthreads();
    if (tid == 0) {
        g_vT[token] = vT;
        g_flag[token] = s_flag;
    }
}

// =====================================================================
// Kernel 3b: exact fp64 boundary refinement for flagged tokens
// =====================================================================
__global__ __launch_bounds__(256)
void refine(const float* __restrict__ pre,
            const float* __restrict__ x,
            const float* __restrict__ Wenc,
            float* __restrict__ sparse)
{
    extern __shared__ float srow[];
    __shared__ int    s_band[64];
    __shared__ float  s_ef[64];
    __shared__ double s_red[256];
    __shared__ unsigned int bm[DSAE / 32];
    __shared__ int s_cnt[256], s_base[256];
    __shared__ int s_chosen[64];
    __shared__ int s_nin, s_c, s_nch;

    const int token = blockIdx.x;
    if (!g_flag[token]) return;

    const int tid = threadIdx.x;
    const float vT = g_vT[token];
    const float* prow = pre + (size_t)token * DSAE;

    for (int i = tid; i < DSAE; i += 256) srow[i] = prow[i];
    if (tid == 0) { s_nin = 0; s_c = 0; }
    __syncthreads();

    int nin_local = 0;
    for (int i = tid; i < DSAE; i += 256) {
        float v = srow[i];
        if (v > vT + BAND_EPS) {
            nin_local++;
        } else if (fabsf(v - vT) <= BAND_EPS) {
            int p = atomicAdd(&s_c, 1);
            if (p < 64) s_band[p] = i;
        }
    }
    atomicAdd(&s_nin, nin_local);
    __syncthreads();

    const int c = min(s_c, 64);
    const int need = KSP - s_nin;

    if (tid == 0) {
        for (int a = 1; a < c; a++) {
            int key = s_band[a], b = a - 1;
            for (; b >= 0 && s_band[b] > key; b--) s_band[b + 1] = s_band[b];
            s_band[b + 1] = key;
        }
    }
    __syncthreads();

    const float* xr = x + (size_t)token * DMODEL;
    for (int j = 0; j < c; j++) {
        const float* wr = Wenc + (size_t)s_band[j] * DMODEL;
        double p = 0.0;
        for (int d = tid; d < DMODEL; d += 256)
            p += (double)xr[d] * (double)wr[d];
        s_red[tid] = p;
        __syncthreads();
        for (int off = 128; off > 0; off >>= 1) {
            if (tid < off) s_red[tid] += s_red[tid + off];
            __syncthreads();
        }
        if (tid == 0) s_ef[j] = (float)s_red[0];
        __syncthreads();
    }

    if (tid == 0) {
        bool used[64];
        for (int j = 0; j < c; j++) used[j] = false;
        int nc = 0;
        for (int t = 0; t < need && t < c; t++) {
            int best = -1;
            for (int j = 0; j < c; j++)
                if (!used[j] && (best < 0 || s_ef[j] > s_ef[best])) best = j;
            used[best] = true;
            s_chosen[nc++] = s_band[best];
        }
        s_nch = nc;
    }
    __syncthreads();

    {
        int seg = tid * 64;
        unsigned int b0 = 0, b1 = 0;
        for (int ii = 0; ii < 64; ii++) {
            float v = srow[seg + ii];
            if (v > vT + BAND_EPS) {
                if (ii < 32) b0 |= (1u << ii);
                else         b1 |= (1u << (ii - 32));
            }
        }
        bm[tid * 2]     = b0;
        bm[tid * 2 + 1] = b1;
    }
    __syncthreads();
    if (tid == 0)
        for (int t = 0; t < s_nch; t++) {
            int i = s_chosen[t];
            bm[i >> 5] |= (1u << (i & 31));
        }
    __syncthreads();

    s_cnt[tid] = __popc(bm[tid * 2]) + __popc(bm[tid * 2 + 1]);
    __syncthreads();
    if (tid == 0) {
        int acc = 0;
        for (int q = 0; q < 256; q++) { s_base[q] = acc; acc += s_cnt[q]; }
    }
    __syncthreads();

    float* srow_out = sparse + (size_t)token * DSAE;
    int*   oidx = g_topidx + (size_t)token * KSP;
    float* oval = g_topval + (size_t)token * KSP;
    {
        int seg = tid * 64;
        int p = s_base[tid];
        for (int ii = 0; ii < 64; ii++) {
            int i = seg + ii;
            bool sel = (bm[i >> 5] >> (i & 31)) & 1u;
            srow_out[i] = sel ? srow[i] : 0.0f;
            if (sel) { oidx[p] = i; oval[p] = srow[i]; p++; }
        }
    }
}

// =====================================================================
// Kernel 4: sparse decoder
// =====================================================================
__global__ __launch_bounds__(256)
void sparse_decode(const float* __restrict__ bdec,
                   float* __restrict__ recon)
{
    const int token = blockIdx.x;
    const int chunk = blockIdx.y * 1024;
    const int t = threadIdx.x;

    __shared__ int   fi[KSP];
    __shared__ float fv[KSP];
    if (t < KSP) {
        fi[t] = g_topidx[(size_t)token * KSP + t];
        fv[t] = g_topval[(size_t)token * KSP + t];
    }
    __syncthreads();

    float a0 = bdec[chunk + t];
    float a1 = bdec[chunk + 256 + t];
    float a2 = bdec[chunk + 512 + t];
    float a3 = bdec[chunk + 768 + t];

#pragma unroll 4
    for (int j = 0; j < KSP; j++) {
        const float* w = g_WdecT + (size_t)fi[j] * DMODEL + chunk;
        float v = fv[j];
        a0 = fmaf(v, w[t], a0);
        a1 = fmaf(v, w[256 + t], a1);
        a2 = fmaf(v, w[512 + t], a2);
        a3 = fmaf(v, w[768 + t], a3);
    }

    float* o = recon + (size_t)token * DMODEL + chunk;
    o[t]       = a0;
    o[256 + t] = a1;
    o[512 + t] = a2;
    o[768 + t] = a3;
}

// =====================================================================
// launch
// =====================================================================
extern "C" void kernel_launch(void* const* d_in, const int* in_sizes, int n_in,
                              void* d_out, int out_size)
{
    const float* x     = (const float*)d_in[0];
    const float* W_enc = (const float*)d_in[1];
    const float* b_enc = (const float*)d_in[2];
    const float* W_dec = (const float*)d_in[3];
    const float* b_dec = (const float*)d_in[4];

    float* out    = (float*)d_out;
    float* recon  = out;
    float* sparse = out + (size_t)NTOK * DMODEL;
    float* pre    = sparse + (size_t)NTOK * DSAE;

    cudaFuncSetAttribute(topk_select, cudaFuncAttributeMaxDynamicSharedMemorySize,
                         DSAE * (int)sizeof(float));
    cudaFuncSetAttribute(refine, cudaFuncAttributeMaxDynamicSharedMemorySize,
                         DSAE * (int)sizeof(float));
    cudaFuncSetAttribute(enc_hmma, cudaFuncAttributeMaxDynamicSharedMemorySize,
                         HB_SMEM);

    __nv_bfloat16 *Ahi, *Amid, *Bhi, *Bmid;
    cudaGetSymbolAddress((void**)&Ahi,  g_Ahi);
    cudaGetSymbolAddress((void**)&Amid, g_Amid);
    cudaGetSymbolAddress((void**)&Bhi,  g_Bhi);
    cudaGetSymbolAddress((void**)&Bmid, g_Bmid);

    // bf16 splits of x and W_enc
    split_pair<<<2048, 256>>>(x,     Ahi, Amid, (size_t)NTOK * DMODEL);
    split_pair<<<4096, 256>>>(W_enc, Bhi, Bmid, (size_t)DSAE * DMODEL);

    // HMMA encoder GEMM -> pre_acts (+bias)
    enc_hmma<<<(NTOK / HB_BM) * (DSAE / HB_BN), 256, HB_SMEM>>>(b_enc, pre);

    // transpose decoder weights
    wdec_transpose<<<dim3(DSAE / 32, DMODEL / 32), dim3(32, 8)>>>(W_dec);

    // per-token top-64 -> sparse_acts + compacted lists + ambiguity flags
    topk_select<<<NTOK, 256, DSAE * sizeof(float)>>>(pre, sparse);

    // exact fp64 boundary refinement
    refine<<<NTOK, 256, DSAE * sizeof(float)>>>(pre, x, W_enc, sparse);

    // sparse decode -> reconstruction
    sparse_decode<<<dim3(NTOK, DMODEL / 1024), 256>>>(b_dec, recon);
}

// round 10
// speedup vs baseline: 2.2444x; 1.5273x over previous
#include <cuda_runtime.h>
#include <cuda_bf16.h>
#include <cstdint>

// Problem constants
#define NTOK   8192
#define DMODEL 4096
#define DSAE   16384
#define KSP    64

#define BAND_EPS 2e-4f   // boundary-ambiguity band on pre_act value scale

// d_out layout: [recon (NTOK*DMODEL) | sparse (NTOK*DSAE) | pre (NTOK*DSAE)]

// ---------------- scratch (__device__ globals) ----------------
__device__ float g_WdecT[(size_t)DSAE * DMODEL];   // 256 MB transposed decoder weights
__device__ int   g_topidx[(size_t)NTOK * KSP];
__device__ float g_topval[(size_t)NTOK * KSP];
__device__ float g_vT[NTOK];
__device__ int   g_flag[NTOK];
// bf16 split operands for tensor-core encoder
__device__ __nv_bfloat16 g_Ahi[(size_t)NTOK * DMODEL];   // 64 MB
__device__ __nv_bfloat16 g_Amid[(size_t)NTOK * DMODEL];  // 64 MB
__device__ __nv_bfloat16 g_Bhi[(size_t)DSAE * DMODEL];   // 128 MB
__device__ __nv_bfloat16 g_Bmid[(size_t)DSAE * DMODEL];  // 128 MB

// ---------------- baseline-PTX helpers (sm_80-level only; NO _a features) -----
__device__ __forceinline__ uint32_t smem_to_u32(const void* p) {
    uint32_t a;
    asm("{ .reg .u64 t; cvta.to.shared.u64 t, %1; cvt.u32.u64 %0, t; }"
        : "=r"(a) : "l"(p));
    return a;
}
__device__ __forceinline__ void cp_async16(uint32_t saddr, const void* gaddr) {
    asm volatile("cp.async.cg.shared.global [%0], [%1], 16;" :: "r"(saddr), "l"(gaddr));
}
#define CP_COMMIT() asm volatile("cp.async.commit_group;" ::: "memory")
template <int N>
__device__ __forceinline__ void cp_wait_group() {
    asm volatile("cp.async.wait_group %0;" :: "n"(N) : "memory");
}

// mma.sync m16n8k16 row.col bf16 -> f32 (PTX ISA 7.0, baseline sm_80)
__device__ __forceinline__ void mma16816(float* d, const uint32_t* a, const uint32_t* b) {
    asm volatile(
        "mma.sync.aligned.m16n8k16.row.col.f32.bf16.bf16.f32 "
        "{%0,%1,%2,%3}, {%4,%5,%6,%7}, {%8,%9}, {%0,%1,%2,%3};"
        : "+f"(d[0]), "+f"(d[1]), "+f"(d[2]), "+f"(d[3])
        : "r"(a[0]), "r"(a[1]), "r"(a[2]), "r"(a[3]), "r"(b[0]), "r"(b[1]));
}

// =====================================================================
// Kernel 0: bf16 two-way split (hi = rn(v), mid = rn(v - hi))
// =====================================================================
__global__ __launch_bounds__(256)
void split_pair(const float* __restrict__ src, __nv_bfloat16* __restrict__ hi,
                __nv_bfloat16* __restrict__ mid, size_t n)
{
    size_t i = (size_t)blockIdx.x * 256 + threadIdx.x;
    size_t stride = (size_t)gridDim.x * 256;
    for (; i < n; i += stride) {
        float v = src[i];
        __nv_bfloat16 h = __float2bfloat16(v);
        float hf = __bfloat162float(h);
        hi[i] = h;
        mid[i] = __float2bfloat16(v - hf);
    }
}

// =====================================================================
// Kernel 1: HMMA encoder GEMM (bf16x3 split):
//   pre = Ahi·Bhi^T + Ahi·Bmid^T + Amid·Bhi^T + bias  (fp32 accum)
// CTA tile 128x256, BK=32, 3-stage cp.async pipeline, 256 threads.
// Each of 8 warps computes a 64x64 sub-tile via m16n8k16 (2x arithmetic
// intensity from smem vs R9's 64x32 -> lifts the LDS-bandwidth ceiling).
// Row stride 80B: fragment LDS covers all 32 banks exactly once.
// =====================================================================
#define HB_BM 128
#define HB_BN 256
#define HB_BK 32
#define HB_RSB 80                        // 64B data (32 bf16) + 16B pad
#define HB_A_MAT (128 * HB_RSB)          // 10240 B
#define HB_B_MAT (256 * HB_RSB)          // 20480 B
#define HB_STAGE (2 * HB_A_MAT + 2 * HB_B_MAT)   // 61440 B
#define HB_NSTAGE 3
#define HB_SMEM (HB_NSTAGE * HB_STAGE)   // 184320 B
#define OFF_AHI  0
#define OFF_AMID HB_A_MAT
#define OFF_BHI  (2 * HB_A_MAT)
#define OFF_BMID (2 * HB_A_MAT + HB_B_MAT)

__global__ __launch_bounds__(256, 1)
void enc_hmma(const float* __restrict__ bias, float* __restrict__ C)
{
    extern __shared__ char smem[];
    const int tid  = threadIdx.x;
    const int wid  = tid >> 5;
    const int lane = tid & 31;

    // rasterize: groups of 8 M-tiles x all 64 N-tiles (A slice L2-resident)
    const int t  = blockIdx.x;
    const int g  = t >> 9;              // /(8*64)
    const int r  = t & 511;
    const int mt = (g << 3) + (r & 7);
    const int nt = r >> 3;
    const int m0 = mt * HB_BM;
    const int n0 = nt * HB_BN;

    const int warp_m = (wid >> 2) * 64;   // 0 / 64
    const int warp_n = (wid & 3) * 64;    // 0..192

    float acc[4][8][4];
#pragma unroll
    for (int i = 0; i < 4; i++)
#pragma unroll
        for (int j = 0; j < 8; j++)
#pragma unroll
            for (int q = 0; q < 4; q++) acc[i][j][q] = 0.0f;

    const uint32_t sb = smem_to_u32(smem);
    const int NCH = DMODEL / HB_BK;      // 128

    // ---- per-thread loader plan: 12 x 16B chunks per stage (3072 total) ----
    uint32_t soff[12];
    const char* gptr[12];
    {
        const char* gAhi  = (const char*)g_Ahi  + (size_t)m0 * DMODEL * 2;
        const char* gAmid = (const char*)g_Amid + (size_t)m0 * DMODEL * 2;
        const char* gBhi  = (const char*)g_Bhi  + (size_t)n0 * DMODEL * 2;
        const char* gBmid = (const char*)g_Bmid + (size_t)n0 * DMODEL * 2;
#pragma unroll
        for (int i = 0; i < 12; i++) {
            int c = tid + i * 256;
            if (c < 1024) {                       // A chunks: 2 mats x 128 rows x 4
                int mat = c >> 9;
                int row = (c >> 2) & 127;
                int col = c & 3;
                soff[i] = (mat ? OFF_AMID : OFF_AHI) + row * HB_RSB + col * 16;
                gptr[i] = (mat ? gAmid : gAhi) + (size_t)row * (DMODEL * 2) + col * 16;
            } else {                              // B chunks: 2 mats x 256 rows x 4
                int cb  = c - 1024;
                int mat = cb >> 10;
                int row = (cb >> 2) & 255;
                int col = cb & 3;
                soff[i] = (mat ? OFF_BMID : OFF_BHI) + row * HB_RSB + col * 16;
                gptr[i] = (mat ? gBmid : gBhi) + (size_t)row * (DMODEL * 2) + col * 16;
            }
        }
    }

    auto load_stage = [&](int ch, int s) {
        const uint32_t stg = sb + s * HB_STAGE;
        const size_t kadv = (size_t)ch * 64;     // 32 bf16 = 64 bytes per chunk
#pragma unroll
        for (int i = 0; i < 12; i++)
            cp_async16(stg + soff[i], gptr[i] + kadv);
        CP_COMMIT();
    };

    load_stage(0, 0);
    load_stage(1, 1);

    const int gg = lane >> 2;
    const int tg = lane & 3;

    for (int ch = 0; ch < NCH; ch++) {
        if (ch + 1 < NCH) cp_wait_group<1>();
        else              cp_wait_group<0>();
        __syncthreads();

        if (ch + 2 < NCH) load_stage(ch + 2, (ch + 2) % 3);

        const char* stg = smem + (ch % 3) * HB_STAGE;

#pragma unroll
        for (int ks = 0; ks < 2; ks++) {
            const int kb = ks * 32;              // 16 bf16 = 32B per k-step
            uint32_t ah[4][4], am[4][4];
#pragma unroll
            for (int i = 0; i < 4; i++) {
                const char* pa = stg + OFF_AHI +
                                 (warp_m + i * 16 + gg) * HB_RSB + kb + tg * 4;
                ah[i][0] = *(const uint32_t*)pa;
                ah[i][1] = *(const uint32_t*)(pa + 8 * HB_RSB);
                ah[i][2] = *(const uint32_t*)(pa + 16);
                ah[i][3] = *(const uint32_t*)(pa + 8 * HB_RSB + 16);
                const char* pm = pa + (OFF_AMID - OFF_AHI);
                am[i][0] = *(const uint32_t*)pm;
                am[i][1] = *(const uint32_t*)(pm + 8 * HB_RSB);
                am[i][2] = *(const uint32_t*)(pm + 16);
                am[i][3] = *(const uint32_t*)(pm + 8 * HB_RSB + 16);
            }
#pragma unroll
            for (int j = 0; j < 8; j++) {
                const char* pb = stg + OFF_BHI +
                                 (warp_n + j * 8 + gg) * HB_RSB + kb + tg * 4;
                uint32_t bh[2], bm2[2];
                bh[0]  = *(const uint32_t*)pb;
                bh[1]  = *(const uint32_t*)(pb + 16);
                const char* pb2 = pb + (OFF_BMID - OFF_BHI);
                bm2[0] = *(const uint32_t*)pb2;
                bm2[1] = *(const uint32_t*)(pb2 + 16);
#pragma unroll
                for (int i = 0; i < 4; i++) {
                    mma16816(acc[i][j], ah[i], bh);
                    mma16816(acc[i][j], ah[i], bm2);
                    mma16816(acc[i][j], am[i], bh);
                }
            }
        }
    }

    // ---- epilogue: bias add + store ----
#pragma unroll
    for (int i = 0; i < 4; i++) {
        const int row0 = m0 + warp_m + i * 16 + gg;
#pragma unroll
        for (int j = 0; j < 8; j++) {
            const int col = n0 + warp_n + j * 8 + tg * 2;
            const float b0 = bias[col];
            const float b1 = bias[col + 1];
            float* p0 = C + (size_t)row0 * DSAE + col;
            float* p1 = C + (size_t)(row0 + 8) * DSAE + col;
            *(float2*)p0 = make_float2(acc[i][j][0] + b0, acc[i][j][1] + b1);
            *(float2*)p1 = make_float2(acc[i][j][2] + b0, acc[i][j][3] + b1);
        }
    }
}

// =====================================================================
// Kernel 2: transpose W_dec (DMODEL x DSAE) -> g_WdecT (DSAE x DMODEL)
// =====================================================================
__global__ __launch_bounds__(256)
void wdec_transpose(const float* __restrict__ W)
{
    __shared__ float s[32][33];
    const int f0 = blockIdx.x * 32;
    const int d0 = blockIdx.y * 32;
    const int tx = threadIdx.x;
    const int ty = threadIdx.y;
#pragma unroll
    for (int j = 0; j < 32; j += 8)
        s[ty + j][tx] = W[(size_t)(d0 + ty + j) * DSAE + f0 + tx];
    __syncthreads();
#pragma unroll
    for (int j = 0; j < 32; j += 8)
        g_WdecT[(size_t)(f0 + ty + j) * DMODEL + d0 + tx] = s[tx][ty + j];
}

// =====================================================================
// Kernel 3: per-token top-64 radix select (exact on our fp32 values,
// lowest-index tie-break) + ambiguity flagging
// =====================================================================
__device__ __forceinline__ unsigned int fkey(float x) {
    unsigned int u = __float_as_uint(x);
    unsigned int m = ((unsigned int)((int)u >> 31)) | 0x80000000u;
    return u ^ m;
}
__device__ __forceinline__ float keyval(unsigned int k) {
    unsigned int u = (k & 0x80000000u) ? (k ^ 0x80000000u) : ~k;
    return __uint_as_float(u);
}

__global__ __launch_bounds__(256)
void topk_select(const float* __restrict__ pre, float* __restrict__ sparse)
{
    extern __shared__ float srow[];
    __shared__ unsigned int hist[8][256];
    __shared__ unsigned int bitmap[DSAE / 32];
    __shared__ int s_gt[256], s_eq[256], s_base[256], s_ebase[256];
    __shared__ unsigned int sh_pfx;
    __shared__ int sh_need;
    __shared__ int s_flag;

    const int token = blockIdx.x;
    const int tid = threadIdx.x;
    const int wid = tid >> 5;
    const float* prow = pre + (size_t)token * DSAE;

    for (int i = tid; i < DSAE; i += 256) srow[i] = prow[i];
    __syncthreads();

    unsigned int pfx = 0;
    int need = KSP;
    for (int b = 3; b >= 0; --b) {
        for (int i = tid; i < 8 * 256; i += 256) ((unsigned int*)hist)[i] = 0;
        __syncthreads();
        const int sh = b * 8;
        for (int i = tid; i < DSAE; i += 256) {
            unsigned int k = fkey(srow[i]);
            bool m = (b == 3) || ((k >> (sh + 8)) == pfx);
            if (m) atomicAdd(&hist[wid][(k >> sh) & 255], 1u);
        }
        __syncthreads();
        if (tid < 256) {
            unsigned int s = 0;
#pragma unroll
            for (int w = 0; w < 8; w++) s += hist[w][tid];
            hist[0][tid] = s;
        }
        __syncthreads();
        if (tid == 0) {
            int cum = 0, v = 255;
            for (; v > 0; --v) {
                int c = (int)hist[0][v];
                if (cum + c >= need) break;
                cum += c;
            }
            sh_pfx = (pfx << 8) | (unsigned int)v;
            sh_need = need - cum;
        }
        __syncthreads();
        pfx = sh_pfx;
        need = sh_need;
        __syncthreads();
    }
    const unsigned int T = pfx;
    const int r = need;
    const float vT = keyval(T);

    const int seg = tid * 64;
    {
        int ngt = 0, neq = 0;
#pragma unroll 4
        for (int ii = 0; ii < 64; ii++) {
            unsigned int k = fkey(srow[seg + ii]);
            ngt += (k > T);
            neq += (k == T);
        }
        s_gt[tid] = ngt;
        s_eq[tid] = neq;
    }
    if (tid == 0) s_flag = 0;
    __syncthreads();
    if (tid == 0) {
        int eacc = 0, sacc = 0;
        for (int q = 0; q < 256; q++) {
            s_ebase[q] = eacc;
            int etake = r - eacc;
            if (etake < 0) etake = 0;
            if (etake > s_eq[q]) etake = s_eq[q];
            s_base[q] = sacc;
            sacc += s_gt[q] + etake;
            eacc += s_eq[q];
        }
    }
    __syncthreads();

    {
        unsigned int bits0 = 0, bits1 = 0;
        int p = s_base[tid];
        int e = s_ebase[tid];
        int*   oidx = g_topidx + (size_t)token * KSP;
        float* oval = g_topval + (size_t)token * KSP;
        for (int ii = 0; ii < 64; ii++) {
            int i = seg + ii;
            float x = srow[i];
            unsigned int k = fkey(x);
            bool gt = (k > T);
            bool eq = (k == T);
            bool take = gt || (eq && e < r);
            if (eq) e++;
            if (take) {
                oidx[p] = i;
                oval[p] = x;
                if (ii < 32) bits0 |= (1u << ii);
                else         bits1 |= (1u << (ii - 32));
                p++;
            }
        }
        bitmap[tid * 2]     = bits0;
        bitmap[tid * 2 + 1] = bits1;
    }
    __syncthreads();

    float* srow_out = sparse + (size_t)token * DSAE;
    for (int i = tid; i < DSAE; i += 256) {
        bool sel = (bitmap[i >> 5] >> (i & 31)) & 1u;
        float v = srow[i];
        srow_out[i] = sel ? v : 0.0f;
        if (!sel && fabsf(v - vT) <= BAND_EPS) s_flag = 1;
    }
    __syncthreads();
    if (tid == 0) {
        g_vT[token] = vT;
        g_flag[token] = s_flag;
    }
}

// =====================================================================
// Kernel 3b: exact fp64 boundary refinement for flagged tokens
// =====================================================================
__global__ __launch_bounds__(256)
void refine(const float* __restrict__ pre,
            const float* __restrict__ x,
            const float* __restrict__ Wenc,
            float* __restrict__ sparse)
{
    extern __shared__ float srow[];
    __shared__ int    s_band[64];
    __shared__ float  s_ef[64];
    __shared__ double s_red[256];
    __shared__ unsigned int bm[DSAE / 32];
    __shared__ int s_cnt[256], s_base[256];
    __shared__ int s_chosen[64];
    __shared__ int s_nin, s_c, s_nch;

    const int token = blockIdx.x;
    if (!g_flag[token]) return;

    const int tid = threadIdx.x;
    const float vT = g_vT[token];
    const float* prow = pre + (size_t)token * DSAE;

    for (int i = tid; i < DSAE; i += 256) srow[i] = prow[i];
    if (tid == 0) { s_nin = 0; s_c = 0; }
    __syncthreads();

    int nin_local = 0;
    for (int i = tid; i < DSAE; i += 256) {
        float v = srow[i];
        if (v > vT + BAND_EPS) {
            nin_local++;
        } else if (fabsf(v - vT) <= BAND_EPS) {
            int p = atomicAdd(&s_c, 1);
            if (p < 64) s_band[p] = i;
        }
    }
    atomicAdd(&s_nin, nin_local);
    __syncthreads();

    const int c = min(s_c, 64);
    const int need = KSP - s_nin;

    if (tid == 0) {
        for (int a = 1; a < c; a++) {
            int key = s_band[a], b = a - 1;
            for (; b >= 0 && s_band[b] > key; b--) s_band[b + 1] = s_band[b];
            s_band[b + 1] = key;
        }
    }
    __syncthreads();

    const float* xr = x + (size_t)token * DMODEL;
    for (int j = 0; j < c; j++) {
        const float* wr = Wenc + (size_t)s_band[j] * DMODEL;
        double p = 0.0;
        for (int d = tid; d < DMODEL; d += 256)
            p += (double)xr[d] * (double)wr[d];
        s_red[tid] = p;
        __syncthreads();
        for (int off = 128; off > 0; off >>= 1) {
            if (tid < off) s_red[tid] += s_red[tid + off];
            __syncthreads();
        }
        if (tid == 0) s_ef[j] = (float)s_red[0];
        __syncthreads();
    }

    if (tid == 0) {
        bool used[64];
        for (int j = 0; j < c; j++) used[j] = false;
        int nc = 0;
        for (int t = 0; t < need && t < c; t++) {
            int best = -1;
            for (int j = 0; j < c; j++)
                if (!used[j] && (best < 0 || s_ef[j] > s_ef[best])) best = j;
            used[best] = true;
            s_chosen[nc++] = s_band[best];
        }
        s_nch = nc;
    }
    __syncthreads();

    {
        int seg = tid * 64;
        unsigned int b0 = 0, b1 = 0;
        for (int ii = 0; ii < 64; ii++) {
            float v = srow[seg + ii];
            if (v > vT + BAND_EPS) {
                if (ii < 32) b0 |= (1u << ii);
                else         b1 |= (1u << (ii - 32));
            }
        }
        bm[tid * 2]     = b0;
        bm[tid * 2 + 1] = b1;
    }
    __syncthreads();
    if (tid == 0)
        for (int t = 0; t < s_nch; t++) {
            int i = s_chosen[t];
            bm[i >> 5] |= (1u << (i & 31));
        }
    __syncthreads();

    s_cnt[tid] = __popc(bm[tid * 2]) + __popc(bm[tid * 2 + 1]);
    __syncthreads();
    if (tid == 0) {
        int acc = 0;
        for (int q = 0; q < 256; q++) { s_base[q] = acc; acc += s_cnt[q]; }
    }
    __syncthreads();

    float* srow_out = sparse + (size_t)token * DSAE;
    int*   oidx = g_topidx + (size_t)token * KSP;
    float* oval = g_topval + (size_t)token * KSP;
    {
        int seg = tid * 64;
        int p = s_base[tid];
        for (int ii = 0; ii < 64; ii++) {
            int i = seg + ii;
            bool sel = (bm[i >> 5] >> (i & 31)) & 1u;
            srow_out[i] = sel ? srow[i] : 0.0f;
            if (sel) { oidx[p] = i; oval[p] = srow[i]; p++; }
        }
    }
}

// =====================================================================
// Kernel 4: sparse decoder
// =====================================================================
__global__ __launch_bounds__(256)
void sparse_decode(const float* __restrict__ bdec,
                   float* __restrict__ recon)
{
    const int token = blockIdx.x;
    const int chunk = blockIdx.y * 1024;
    const int t = threadIdx.x;

    __shared__ int   fi[KSP];
    __shared__ float fv[KSP];
    if (t < KSP) {
        fi[t] = g_topidx[(size_t)token * KSP + t];
        fv[t] = g_topval[(size_t)token * KSP + t];
    }
    __syncthreads();

    float a0 = bdec[chunk + t];
    float a1 = bdec[chunk + 256 + t];
    float a2 = bdec[chunk + 512 + t];
    float a3 = bdec[chunk + 768 + t];

#pragma unroll 4
    for (int j = 0; j < KSP; j++) {
        const float* w = g_WdecT + (size_t)fi[j] * DMODEL + chunk;
        float v = fv[j];
        a0 = fmaf(v, w[t], a0);
        a1 = fmaf(v, w[256 + t], a1);
        a2 = fmaf(v, w[512 + t], a2);
        a3 = fmaf(v, w[768 + t], a3);
    }

    float* o = recon + (size_t)token * DMODEL + chunk;
    o[t]       = a0;
    o[256 + t] = a1;
    o[512 + t] = a2;
    o[768 + t] = a3;
}

// =====================================================================
// launch
// =====================================================================
extern "C" void kernel_launch(void* const* d_in, const int* in_sizes, int n_in,
                              void* d_out, int out_size)
{
    const float* x     = (const float*)d_in[0];
    const float* W_enc = (const float*)d_in[1];
    const float* b_enc = (const float*)d_in[2];
    const float* W_dec = (const float*)d_in[3];
    const float* b_dec = (const float*)d_in[4];

    float* out    = (float*)d_out;
    float* recon  = out;
    float* sparse = out + (size_t)NTOK * DMODEL;
    float* pre    = sparse + (size_t)NTOK * DSAE;

    cudaFuncSetAttribute(topk_select, cudaFuncAttributeMaxDynamicSharedMemorySize,
                         DSAE * (int)sizeof(float));
    cudaFuncSetAttribute(refine, cudaFuncAttributeMaxDynamicSharedMemorySize,
                         DSAE * (int)sizeof(float));
    cudaFuncSetAttribute(enc_hmma, cudaFuncAttributeMaxDynamicSharedMemorySize,
                         HB_SMEM);

    __nv_bfloat16 *Ahi, *Amid, *Bhi, *Bmid;
    cudaGetSymbolAddress((void**)&Ahi,  g_Ahi);
    cudaGetSymbolAddress((void**)&Amid, g_Amid);
    cudaGetSymbolAddress((void**)&Bhi,  g_Bhi);
    cudaGetSymbolAddress((void**)&Bmid, g_Bmid);

    // bf16 splits of x and W_enc
    split_pair<<<2048, 256>>>(x,     Ahi, Amid, (size_t)NTOK * DMODEL);
    split_pair<<<4096, 256>>>(W_enc, Bhi, Bmid, (size_t)DSAE * DMODEL);

    // HMMA encoder GEMM -> pre_acts (+bias), 64x64 warp tiles
    enc_hmma<<<(NTOK / HB_BM) * (DSAE / HB_BN), 256, HB_SMEM>>>(b_enc, pre);

    // transpose decoder weights
    wdec_transpose<<<dim3(DSAE / 32, DMODEL / 32), dim3(32, 8)>>>(W_dec);

    // per-token top-64 -> sparse_acts + compacted lists + ambiguity flags
    topk_select<<<NTOK, 256, DSAE * sizeof(float)>>>(pre, sparse);

    // exact fp64 boundary refinement
    refine<<<NTOK, 256, DSAE * sizeof(float)>>>(pre, x, W_enc, sparse);

    // sparse decode -> reconstruction
    sparse_decode<<<dim3(NTOK, DMODEL / 1024), 256>>>(b_dec, recon);
}